// round 12
// baseline (speedup 1.0000x reference)
#include <cuda_runtime.h>
#include <cstdint>

// SoftMaxPlus: out[b, :] = cumsum(softplus(beta * c[b, :]) / beta) along S.
// B=4096 rows, S=8192 cols, fp32.
// CTA-per-row, ticket-balanced (self-resetting), depth-3 per-thread cp.async
// ring. EARLY REFILL: slot refilled right after its LDS reads (each thread
// overwrites only bytes it alone reads) -> fill traffic flows during the scan.
// Packed f32x2 polynomial softplus (1 MUFU/elem, FFMA2 pipe ops).

constexpr int S_LEN    = 8192;
constexpr int NTHREADS = 512;
constexpr int NWARPS   = 16;
constexpr int GROUPS   = 4;      // 4 float4 segments per thread
constexpr int DEPTH    = 3;      // ring depth (rows)
constexpr int QN       = 8;      // row-id queue size (power of 2, >= DEPTH+2)
constexpr int GRID     = 304;    // 152 SMs x 2 CTAs

__device__ unsigned g_ticket;    // zero at load; self-resets each run
__device__ unsigned g_done;

// ---- packed f32x2 helpers ----
__device__ __forceinline__ unsigned long long pk2(float lo, float hi)
{
    unsigned long long r;
    asm("mov.b64 %0, {%1, %2};" : "=l"(r) : "f"(lo), "f"(hi));
    return r;
}
__device__ __forceinline__ void upk2(float& lo, float& hi, unsigned long long v)
{
    asm("mov.b64 {%0, %1}, %2;" : "=f"(lo), "=f"(hi) : "l"(v));
}
__device__ __forceinline__ unsigned long long fma2(unsigned long long a,
                                                   unsigned long long b,
                                                   unsigned long long c)
{
    unsigned long long d;
    asm("fma.rn.f32x2 %0, %1, %2, %3;" : "=l"(d) : "l"(a), "l"(b), "l"(c));
    return d;
}
__device__ __forceinline__ unsigned long long mul2(unsigned long long a,
                                                   unsigned long long b)
{
    unsigned long long d;
    asm("mul.rn.f32x2 %0, %1, %2;" : "=l"(d) : "l"(a), "l"(b));
    return d;
}
__device__ __forceinline__ unsigned long long add2(unsigned long long a,
                                                   unsigned long long b)
{
    unsigned long long d;
    asm("add.rn.f32x2 %0, %1, %2;" : "=l"(d) : "l"(a), "l"(b));
    return d;
}

__device__ __forceinline__ void cp16(float* smem_dst, const float* gsrc)
{
    unsigned s = (unsigned)__cvta_generic_to_shared(smem_dst);
    asm volatile("cp.async.cg.shared.global [%0], [%1], 16;\n" :: "r"(s), "l"(gsrc));
}

// Prefetch one full row into a ring slot. Always commits exactly one group.
__device__ __forceinline__ void prefetch_row(float* slot, const float* __restrict__ c,
                                             unsigned row, int nrows, int w, int l)
{
    if (row < (unsigned)nrows) {
        const float* src = c + (long long)row * S_LEN;
#pragma unroll
        for (int g = 0; g < GROUPS; g++) {
            const int idx = ((w * GROUPS + g) * 32 + l) * 4;
            cp16(slot + idx, src + idx);
        }
    }
    asm volatile("cp.async.commit_group;\n" ::: "memory");
}

extern __shared__ float ring[];            // DEPTH * S_LEN floats (96 KB)

__global__ __launch_bounds__(NTHREADS, 2)
void softmaxplus_scan_kernel(const float* __restrict__ c,
                             const float* __restrict__ beta_ptr,
                             float* __restrict__ out,
                             int nrows)
{
    __shared__ unsigned rowq[QN];
    __shared__ float    tot[2][NWARPS];

    const int t = threadIdx.x;
    const int w = t >> 5;
    const int l = t & 31;

    const float beta = __ldg(beta_ptr);
    const float kE = -beta * 1.4426950408889634f;    // -beta*log2(e)
    const float kL = 0.6931471805599453f / beta;     // ln2/beta
    // deg-4 interp of log2(1+u) on [0,1], folded with kL; packed duplicates:
    const unsigned long long AA = pk2(-0.07847512f * kL, -0.07847512f * kL);
    const unsigned long long BB = pk2( 0.31239740f * kL,  0.31239740f * kL);
    const unsigned long long CC = pk2(-0.67111465f * kL, -0.67111465f * kL);
    const unsigned long long DD = pk2( 1.43719237f * kL,  1.43719237f * kL);

    // ---- prologue: pull DEPTH+1 tickets, publish, fill the ring ----
    if (t == 0) {
#pragma unroll
        for (int d = 0; d <= DEPTH; d++) rowq[d] = atomicAdd(&g_ticket, 1u);
    }
    __syncthreads();
#pragma unroll
    for (int d = 0; d < DEPTH; d++)
        prefetch_row(ring + d * S_LEN, c, rowq[d], nrows, w, l);

    int it = 0;
    for (;;) {
        const unsigned row = rowq[it & (QN - 1)];
        if (row >= (unsigned)nrows) {
            asm volatile("cp.async.wait_all;\n" ::: "memory");
            break;
        }

        asm volatile("cp.async.wait_group %0;\n" :: "n"(DEPTH - 1) : "memory");

        const int slot = it % DEPTH;
        const float* sbuf = ring + slot * S_LEN;

        // ---- read own 16 floats from smem ----
        float4 vv[GROUPS];
#pragma unroll
        for (int g = 0; g < GROUPS; g++)
            vv[g] = *reinterpret_cast<const float4*>(sbuf + ((w * GROUPS + g) * 32 + l) * 4);

        // EARLY REFILL: this thread's slot bytes are now in registers; the
        // target row id rowq[it+DEPTH] was published at iteration it-1's
        // barrier (prologue for it==0). No barrier needed before reuse.
        prefetch_row(ring + slot * S_LEN, c, rowq[(it + DEPTH) & (QN - 1)], nrows, w, l);

        // pull the NEXT ticket (published by this iteration's barrier)
        if (t == 0) rowq[(it + DEPTH + 1) & (QN - 1)] = atomicAdd(&g_ticket, 1u);

        // ---- elementwise (packed poly) + per-thread prefix + warp scans ----
        float p[GROUPS][4], texcl[GROUPS], gtot[GROUPS];
#pragma unroll
        for (int g = 0; g < GROUPS; g++) {
            const float4 v = vv[g];
            float u0 = exp2f(kE * fabsf(v.x));
            float u1 = exp2f(kE * fabsf(v.y));
            float u2 = exp2f(kE * fabsf(v.z));
            float u3 = exp2f(kE * fabsf(v.w));
            unsigned long long u01 = pk2(u0, u1), u23 = pk2(u2, u3);
            unsigned long long t01 = fma2(AA, u01, BB);
            unsigned long long t23 = fma2(AA, u23, BB);
            t01 = fma2(t01, u01, CC);  t23 = fma2(t23, u23, CC);
            t01 = fma2(t01, u01, DD);  t23 = fma2(t23, u23, DD);
            t01 = mul2(t01, u01);      t23 = mul2(t23, u23);
            unsigned long long b01 = pk2(fmaxf(v.x, 0.0f), fmaxf(v.y, 0.0f));
            unsigned long long b23 = pk2(fmaxf(v.z, 0.0f), fmaxf(v.w, 0.0f));
            unsigned long long r01 = add2(b01, t01), r23 = add2(b23, t23);
            float f0, f1, f2, f3;
            upk2(f0, f1, r01);
            upk2(f2, f3, r23);

            p[g][0] = f0;
            p[g][1] = p[g][0] + f1;
            p[g][2] = p[g][1] + f2;
            p[g][3] = p[g][2] + f3;
            float ws = p[g][3];
#pragma unroll
            for (int o = 1; o < 32; o <<= 1) {
                float y = __shfl_up_sync(0xFFFFFFFFu, ws, o);
                if (l >= o) ws += y;
            }
            texcl[g] = ws - p[g][3];
            gtot[g]  = __shfl_sync(0xFFFFFFFFu, ws, 31);
        }

        const float ge1 = gtot[0];
        const float ge2 = ge1 + gtot[1];
        const float ge3 = ge2 + gtot[2];
        const float wtot = ge3 + gtot[3];

        float* tb = tot[it & 1];
        if (l == 0) tb[w] = wtot;
        __syncthreads();   // publishes warp totals AND the new rowq entry

        // exclusive sum of warp totals for warps < w (masked butterfly)
        float m = (l < w) ? tb[l] : 0.0f;
#pragma unroll
        for (int o = 16; o >= 1; o >>= 1)
            m += __shfl_xor_sync(0xFFFFFFFFu, m, o);

        const float offs[GROUPS] = {m, m + ge1, m + ge2, m + ge3};

        float* rowout = out + (long long)row * S_LEN;
#pragma unroll
        for (int g = 0; g < GROUPS; g++) {
            const float o = offs[g] + texcl[g];
            float4 r = make_float4(p[g][0] + o, p[g][1] + o, p[g][2] + o, p[g][3] + o);
            __stcs(reinterpret_cast<float4*>(rowout + ((w * GROUPS + g) * 32 + l) * 4), r);
        }

        it++;
    }

    // ---- self-reset of the global ticket (no extra launch in the graph) ----
    if (t == 0) {
        __threadfence();
        unsigned d = atomicAdd(&g_done, 1u);
        if (d == (unsigned)gridDim.x - 1u) {
            g_ticket = 0u;
            g_done   = 0u;
            __threadfence();
        }
    }
}

extern "C" void kernel_launch(void* const* d_in, const int* in_sizes, int n_in,
                              void* d_out, int out_size)
{
    const float* c    = (const float*)d_in[0];
    const float* beta = (const float*)d_in[1];
    float* out        = (float*)d_out;

    const int nrows = in_sizes[0] / S_LEN;   // 4096
    const int smem_bytes = DEPTH * S_LEN * sizeof(float);  // 96 KB

    static bool attr_set = false;
    if (!attr_set) {
        cudaFuncSetAttribute(softmaxplus_scan_kernel,
                             cudaFuncAttributeMaxDynamicSharedMemorySize, smem_bytes);
        attr_set = true;
    }

    softmaxplus_scan_kernel<<<GRID, NTHREADS, smem_bytes>>>(c, beta, out, nrows);
}